// round 14
// baseline (speedup 1.0000x reference)
#include <cuda_runtime.h>
#include <cuda_bf16.h>
#include <cstdint>
#include <math.h>

// Shapes (fixed)
#define BB 32
#define TT 4
#define LL 196
#define DD 512
#define HH 8
#define ROWS (BB*TT*LL)          // 25088

// Scratch (device globals)
__device__ float g_Yq[(size_t)ROWS * DD];
__device__ float g_Yk[(size_t)ROWS * DD];
__device__ float g_Yv[(size_t)ROWS * DD];
__device__ __nv_bfloat16 g_xs[3 * (size_t)ROWS * DD];   // x split planes
__device__ __nv_bfloat16 g_ws[12 * (size_t)DD * DD];    // 4 weights x 3 planes
__device__ __nv_bfloat16 g_s2b[(size_t)ROWS * DD];      // attn-LIF spikes (bf16 exact)
__device__ unsigned long long g_qb[TT*BB*HH*LL];
__device__ unsigned long long g_kb[TT*BB*HH*LL];
__device__ unsigned long long g_vb[TT*BB*HH*LL];

// ---------------------------------------------------------------------------
// split helpers (bf16 3-way: residual ~2^-27 — the proven-safe class)
// ---------------------------------------------------------------------------
__device__ __forceinline__ void split3(float f, float& s0, float& s1, float& s2) {
    s0 = __bfloat162float(__float2bfloat16_rn(f));
    float r1 = f - s0;
    s1 = __bfloat162float(__float2bfloat16_rn(r1));
    s2 = r1 - s1;
}

__device__ __forceinline__ void split_store(
    const float* __restrict__ X, __nv_bfloat16* __restrict__ P0,
    __nv_bfloat16* __restrict__ P1, __nv_bfloat16* __restrict__ P2, size_t idx)
{
    float4 v = *(const float4*)(X + idx);
    float a0,a1,a2,b0,b1,b2,c0,c1,c2,d0,d1,d2;
    split3(v.x, a0,a1,a2); split3(v.y, b0,b1,b2);
    split3(v.z, c0,c1,c2); split3(v.w, d0,d1,d2);
    *(__nv_bfloat162*)(P0 + idx)     = __nv_bfloat162(__float2bfloat16_rn(a0), __float2bfloat16_rn(b0));
    *(__nv_bfloat162*)(P0 + idx + 2) = __nv_bfloat162(__float2bfloat16_rn(c0), __float2bfloat16_rn(d0));
    *(__nv_bfloat162*)(P1 + idx)     = __nv_bfloat162(__float2bfloat16_rn(a1), __float2bfloat16_rn(b1));
    *(__nv_bfloat162*)(P1 + idx + 2) = __nv_bfloat162(__float2bfloat16_rn(c1), __float2bfloat16_rn(d1));
    *(__nv_bfloat162*)(P2 + idx)     = __nv_bfloat162(__float2bfloat16_rn(a2), __float2bfloat16_rn(b2));
    *(__nv_bfloat162*)(P2 + idx + 2) = __nv_bfloat162(__float2bfloat16_rn(c2), __float2bfloat16_rn(d2));
}

// ONE launch for all splits: blocks [0, NXB) do x, [NXB, NXB+4*256) do weights.
#define NXB ((unsigned)(((size_t)ROWS * DD) / 1024))   // 12544

__global__ void __launch_bounds__(256) split_all_kernel(
    const float* __restrict__ X, __nv_bfloat16* __restrict__ XS,
    const float* __restrict__ W0, const float* __restrict__ W1,
    const float* __restrict__ W2, const float* __restrict__ W3,
    __nv_bfloat16* __restrict__ WS)
{
    const size_t nX = (size_t)ROWS * DD;
    const size_t nW = (size_t)DD * DD;
    if (blockIdx.x < NXB) {
        const size_t idx = ((size_t)blockIdx.x * 256 + threadIdx.x) * 4;
        if (idx < nX) split_store(X, XS, XS + nX, XS + 2 * nX, idx);
    } else {
        const unsigned wb = blockIdx.x - NXB;
        const int wsel = wb >> 8;
        const float* W = (wsel == 0) ? W0 : (wsel == 1) ? W1 : (wsel == 2) ? W2 : W3;
        __nv_bfloat16* base = WS + (size_t)wsel * 3 * nW;
        const size_t idx = ((size_t)(wb & 255) * 256 + threadIdx.x) * 4;
        if (idx < nW) split_store(W, base, base + nW, base + 2 * nW, idx);
    }
}

// ---------------------------------------------------------------------------
// bf16x3 GEMM, ldmatrix + 4-stage cp.async (wait_group 2), ni-inner mma order,
// prefetch after compute. All measured-best choices (R12 = 1234.7us config).
// Per-accumulator term order t-ascending -> bit-identical results.
// ---------------------------------------------------------------------------
__device__ __forceinline__ void mma_bf16(float* c, const uint32_t* a, const uint32_t* b) {
    asm volatile(
        "mma.sync.aligned.m16n8k16.row.col.f32.bf16.bf16.f32 "
        "{%0,%1,%2,%3}, {%4,%5,%6,%7}, {%8,%9}, {%0,%1,%2,%3};\n"
        : "+f"(c[0]), "+f"(c[1]), "+f"(c[2]), "+f"(c[3])
        : "r"(a[0]), "r"(a[1]), "r"(a[2]), "r"(a[3]), "r"(b[0]), "r"(b[1]));
}

__device__ __forceinline__ void ldsm_x4(uint32_t& d0, uint32_t& d1, uint32_t& d2,
                                        uint32_t& d3, uint32_t addr) {
    asm volatile("ldmatrix.sync.aligned.m8n8.x4.shared.b16 {%0,%1,%2,%3}, [%4];"
                 : "=r"(d0), "=r"(d1), "=r"(d2), "=r"(d3) : "r"(addr));
}

template <bool EXACT_A>
__global__ void __launch_bounds__(256, 2) gemm_pre_kernel(
    const __nv_bfloat16* __restrict__ Ap,
    const __nv_bfloat16* __restrict__ BpBase,
    const float* __restrict__ bias0, const float* __restrict__ bias1,
    const float* __restrict__ bias2,
    float* __restrict__ C0, float* __restrict__ C1, float* __restrict__ C2)
{
    constexpr int APL = EXACT_A ? 1 : 3;
    constexpr int ASZ = APL * 4096;
    constexpr int BSZ = 3 * 4096;
    constexpr int STG = ASZ + BSZ;

    extern __shared__ char smem[];
    const uint32_t sbase = (uint32_t)__cvta_generic_to_shared(smem);

    const int z = blockIdx.z;
    const __nv_bfloat16* Bp = BpBase + (size_t)z * 3 * ((size_t)DD * DD);
    const float* bias = (z == 0) ? bias0 : (z == 1) ? bias1 : bias2;
    float* C = (z == 0) ? C0 : (z == 1) ? C1 : C2;

    const int tid = threadIdx.x;
    const int bn = blockIdx.x * 128, bm = blockIdx.y * 128;
    const int w = tid >> 5, lane = tid & 31;
    const int wm = (w & 1) * 64, wn = (w >> 1) * 32;
    const int g = lane >> 2, tg = lane & 3;

    const int lrow = tid >> 1;
    const int kh = tid & 1;
    const int dstoff = (kh * 512 + lrow * 4) * 4;

    const int rowW = lane & 7;
    const int plus8 = (lane >> 3) & 1;
    const int halfsel = (lane >> 4) & 1;
    const int aLane = halfsel * 2048 + (wm + plus8 * 8 + rowW) * 16;
    const int bLane = (wn + (lane >> 3) * 8 + rowW) * 16;

    float acc[4][4][4];
#pragma unroll
    for (int mi = 0; mi < 4; mi++)
#pragma unroll
        for (int ni = 0; ni < 4; ni++)
#pragma unroll
            for (int r = 0; r < 4; r++) acc[mi][ni][r] = 0.f;

    auto stage_load = [&](int buf, int k0) {
        const uint32_t aBase = sbase + buf * STG + dstoff;
        const uint32_t bBase = sbase + buf * STG + ASZ + dstoff;
#pragma unroll
        for (int p = 0; p < APL; p++) {
            const __nv_bfloat16* src = Ap + (size_t)p * ((size_t)ROWS * DD)
                                          + (size_t)(bm + lrow) * DD + k0 + kh * 8;
            asm volatile("cp.async.cg.shared.global [%0], [%1], 16;\n"
                         :: "r"(aBase + p * 4096), "l"(src));
        }
#pragma unroll
        for (int p = 0; p < 3; p++) {
            const __nv_bfloat16* src = Bp + (size_t)p * ((size_t)DD * DD)
                                          + (size_t)(bn + lrow) * DD + k0 + kh * 8;
            asm volatile("cp.async.cg.shared.global [%0], [%1], 16;\n"
                         :: "r"(bBase + p * 4096), "l"(src));
        }
        asm volatile("cp.async.commit_group;\n");
    };

    stage_load(0, 0);
    stage_load(1, 16);
    stage_load(2, 32);

    for (int s = 0; s < 32; s++) {
        const int buf = s & 3;
        if (s < 30) { asm volatile("cp.async.wait_group 2;\n"); }
        else        { asm volatile("cp.async.wait_group 0;\n"); }
        __syncthreads();

        const uint32_t stA = sbase + buf * STG;
        const uint32_t stB = stA + ASZ;

        uint32_t bf[3][4][2];
#pragma unroll
        for (int p = 0; p < 3; p++) {
            ldsm_x4(bf[p][0][0], bf[p][1][0], bf[p][2][0], bf[p][3][0],
                    stB + p * 4096 + bLane);
            ldsm_x4(bf[p][0][1], bf[p][1][1], bf[p][2][1], bf[p][3][1],
                    stB + p * 4096 + 2048 + bLane);
        }

        constexpr int NT = EXACT_A ? 3 : 6;
        const int ta[6] = {0, 0, 0, 1, 1, 2};
        const int tb[6] = {0, 1, 2, 0, 1, 0};

#pragma unroll
        for (int mi = 0; mi < 4; mi++) {
            uint32_t af[APL][4];
#pragma unroll
            for (int p = 0; p < APL; p++)
                ldsm_x4(af[p][0], af[p][1], af[p][2], af[p][3],
                        stA + p * 4096 + aLane + mi * 256);
#pragma unroll
            for (int t = 0; t < NT; t++) {
                const uint32_t* aF = af[EXACT_A ? 0 : ta[t]];
#pragma unroll
                for (int ni = 0; ni < 4; ni++) {
                    uint32_t bb[2] = { bf[tb[t]][ni][0], bf[tb[t]][ni][1] };
                    mma_bf16(acc[mi][ni], aF, bb);
                }
            }
        }

        if (s + 3 < 32) stage_load((s + 3) & 3, (s + 3) * 16);
    }

#pragma unroll
    for (int mi = 0; mi < 4; mi++) {
        const int row = bm + wm + mi * 16 + g;
#pragma unroll
        for (int ni = 0; ni < 4; ni++) {
            const int col = bn + wn + ni * 8 + tg * 2;
            const float b0 = bias[col], b1 = bias[col + 1];
            *(float2*)(C + (size_t)row * DD + col) =
                make_float2(acc[mi][ni][0] + b0, acc[mi][ni][1] + b1);
            *(float2*)(C + (size_t)(row + 8) * DD + col) =
                make_float2(acc[mi][ni][2] + b0, acc[mi][ni][3] + b1);
        }
    }
}

// ---------------------------------------------------------------------------
// Barrier-free LayerNorm + LIF core (bit-identical sums).
// ---------------------------------------------------------------------------
__device__ __forceinline__ void ln_lif_body(
    const float* __restrict__ Y, const float* __restrict__ g,
    const float* __restrict__ be, float thr,
    unsigned long long* __restrict__ bits, float* __restrict__ outf,
    int wg)
{
    const int b = wg / LL, l = wg % LL;
    const int lane = threadIdx.x & 31;

    float vA[8], vB[8];
#pragma unroll
    for (int i = 0; i < 8; i++) { vA[i] = 0.f; vB[i] = 0.f; }

    for (int t = 0; t < TT; t++) {
        const size_t roff = ((size_t)((b * TT + t) * LL + l)) * DD;
        float yA[8], yB[8], s[8];
#pragma unroll
        for (int i = 0; i < 8; i++) {
            yA[i] = Y[roff + i * 64 + lane];
            yB[i] = Y[roff + i * 64 + 32 + lane];
            s[i] = yA[i] + yB[i];
        }
#pragma unroll
        for (int o = 16; o; o >>= 1)
#pragma unroll
            for (int i = 0; i < 8; i++) s[i] += __shfl_xor_sync(0xffffffffu, s[i], o);
        float S = 0.f;
#pragma unroll
        for (int i = 0; i < 8; i++) S += s[i];
        const float mean = S * (1.f / 512.f);

        float q[8];
#pragma unroll
        for (int i = 0; i < 8; i++) {
            const float dA = yA[i] - mean, dB = yB[i] - mean;
            q[i] = dA * dA + dB * dB;
        }
#pragma unroll
        for (int o = 16; o; o >>= 1)
#pragma unroll
            for (int i = 0; i < 8; i++) q[i] += __shfl_xor_sync(0xffffffffu, q[i], o);
        float Q = 0.f;
#pragma unroll
        for (int i = 0; i < 8; i++) Q += q[i];
        const float var = Q * (1.f / 512.f);
        const float rstd = (float)(1.0 / sqrt((double)var + 1e-5));

        unsigned long long rowbits[8];
#pragma unroll
        for (int i = 0; i < 8; i++) {
            const float dA = yA[i] - mean, dB = yB[i] - mean;
            const float nA = dA * rstd * g[i * 64 + lane] + be[i * 64 + lane];
            const float nB = dB * rstd * g[i * 64 + 32 + lane] + be[i * 64 + 32 + lane];
            vA[i] = (vA[i] + nA) * 0.5f;
            vB[i] = (vB[i] + nB) * 0.5f;
            const bool sA = (vA[i] >= thr), sB = (vB[i] >= thr);
            if (sA) vA[i] = 0.f;
            if (sB) vB[i] = 0.f;
            if (bits) {
                unsigned mA = __ballot_sync(0xffffffffu, sA);
                unsigned mB = __ballot_sync(0xffffffffu, sB);
                rowbits[i] = (unsigned long long)mA | ((unsigned long long)mB << 32);
            } else {
                outf[roff + i * 64 + lane]      = sA ? 1.f : 0.f;
                outf[roff + i * 64 + 32 + lane] = sB ? 1.f : 0.f;
            }
        }
        if (bits && lane == 0) {
#pragma unroll
            for (int i = 0; i < 8; i++)
                bits[((size_t)(t * BB + b) * HH + i) * LL + l] = rowbits[i];
        }
    }
}

// Fused Q/K/V LN+LIF: gridDim.y = 3 selects the branch.
__global__ void __launch_bounds__(256, 3) ln_lif3_kernel(
    const float* __restrict__ Y0, const float* __restrict__ Y1,
    const float* __restrict__ Y2,
    const float* __restrict__ g0, const float* __restrict__ g1,
    const float* __restrict__ g2,
    const float* __restrict__ be0, const float* __restrict__ be1,
    const float* __restrict__ be2,
    unsigned long long* __restrict__ b0, unsigned long long* __restrict__ b1,
    unsigned long long* __restrict__ b2)
{
    const int wg = blockIdx.x * 8 + (threadIdx.x >> 5);
    if (wg >= BB * LL) return;
    const int sel = blockIdx.y;
    const float* Y  = (sel == 0) ? Y0 : (sel == 1) ? Y1 : Y2;
    const float* g  = (sel == 0) ? g0 : (sel == 1) ? g1 : g2;
    const float* be = (sel == 0) ? be0 : (sel == 1) ? be1 : be2;
    unsigned long long* bits = (sel == 0) ? b0 : (sel == 1) ? b1 : b2;
    ln_lif_body(Y, g, be, 1.0f, bits, nullptr, wg);
}

// Final LN+LIF (fp32 out).
__global__ void __launch_bounds__(256, 3) ln_lif_kernel(
    const float* __restrict__ Y, const float* __restrict__ g,
    const float* __restrict__ be, float thr,
    unsigned long long* __restrict__ bits, float* __restrict__ outf)
{
    const int wg = blockIdx.x * 8 + (threadIdx.x >> 5);
    if (wg >= BB * LL) return;
    ln_lif_body(Y, g, be, thr, bits, outf, wg);
}

// ---------------------------------------------------------------------------
// Fused attention + attn-LIF (exact integer math).
// ---------------------------------------------------------------------------
#define QROWS 49

__global__ void __launch_bounds__(256) attn_lif_kernel(
    const unsigned long long* __restrict__ qb,
    const unsigned long long* __restrict__ kb,
    const unsigned long long* __restrict__ vb,
    __nv_bfloat16* __restrict__ S2)
{
    __shared__ unsigned long long qs[LL], ks[LL], vs[LL];
    __shared__ uint32_t sKc[64 * 9], sVc[64 * 9];
    __shared__ uint32_t Mw[64 * 17];
    __shared__ uint32_t Qw[QROWS * 16];

    const int blk = blockIdx.x;
    const int qr = blk & 3;
    const int h = (blk >> 2) & 7;
    const int b = blk >> 5;
    const int l0 = qr * QROWS;
    const int tid = threadIdx.x, w = tid >> 5, lane = tid & 31;
    const int cb = h * 64 + lane;

    float vSA[7], vSB[7];
#pragma unroll
    for (int r = 0; r < 7; r++) { vSA[r] = 0.f; vSB[r] = 0.f; }

    for (int t = 0; t < TT; t++) {
        const size_t base = ((size_t)(t * BB + b) * HH + h) * LL;
        if (tid < LL) {
            qs[tid] = qb[base + tid];
            ks[tid] = kb[base + tid];
            vs[tid] = vb[base + tid];
        }
        __syncthreads();

        if (w < 7) {
            const int j = w * 32 + lane;
            const unsigned long long kv = (j < LL) ? ks[j] : 0ull;
            const unsigned long long vv = (j < LL) ? vs[j] : 0ull;
#pragma unroll
            for (int c = 0; c < 64; c++) {
                unsigned mk = __ballot_sync(0xffffffffu, (unsigned)((kv >> c) & 1ull));
                unsigned mv = __ballot_sync(0xffffffffu, (unsigned)((vv >> c) & 1ull));
                if (lane == 0) { sKc[c * 9 + w] = mk; sVc[c * 9 + w] = mv; }
            }
        }
        __syncthreads();

        {
            const int cq = tid & 63;
            const int ib = (tid >> 6) * 4;
            uint32_t vc[7];
#pragma unroll
            for (int u = 0; u < 7; u++) vc[u] = sVc[cq * 9 + u];
#pragma unroll
            for (int wd = 0; wd < 4; wd++) {
                const int i = ib + wd;
                uint32_t word = 0;
#pragma unroll
                for (int r = 0; r < 4; r++) {
                    const int c = 4 * i + r;
                    int s = 0;
#pragma unroll
                    for (int u = 0; u < 7; u++) s += __popc(sKc[c * 9 + u] & vc[u]);
                    word |= (uint32_t)s << (8 * r);
                }
                Mw[cq * 17 + i] = word;
            }
        }
        for (int idx = tid; idx < QROWS * 16; idx += 256) {
            const int l = l0 + (idx >> 4), i = idx & 15;
            const uint32_t nib = (uint32_t)(qs[l] >> (4 * i)) & 0xFu;
            Qw[idx] = (nib * 0x00204081u) & 0x01010101u;
        }
        __syncthreads();

        uint32_t MA[16], MB[16];
#pragma unroll
        for (int i = 0; i < 16; i++) {
            MA[i] = Mw[lane * 17 + i];
            MB[i] = Mw[(lane + 32) * 17 + i];
        }
#pragma unroll
        for (int r = 0; r < 7; r++) {
            const int lr = w + 8 * r;
            if (lr < QROWS) {
                const int l = l0 + lr;
                uint32_t acc0 = 0, acc1 = 0;
                const uint32_t* qrow = &Qw[lr * 16];
#pragma unroll
                for (int i4 = 0; i4 < 16; i4 += 4) {
                    uint4 qv = *(const uint4*)(qrow + i4);
                    acc0 = __dp4a(qv.x, MA[i4 + 0], acc0);
                    acc1 = __dp4a(qv.x, MB[i4 + 0], acc1);
                    acc0 = __dp4a(qv.y, MA[i4 + 1], acc0);
                    acc1 = __dp4a(qv.y, MB[i4 + 1], acc1);
                    acc0 = __dp4a(qv.z, MA[i4 + 2], acc0);
                    acc1 = __dp4a(qv.z, MB[i4 + 2], acc1);
                    acc0 = __dp4a(qv.w, MA[i4 + 3], acc0);
                    acc1 = __dp4a(qv.w, MB[i4 + 3], acc1);
                }
                const float xA = (float)(int)acc0 * 0.25f;
                const float xB = (float)(int)acc1 * 0.25f;
                vSA[r] = (vSA[r] + xA) * 0.5f;
                vSB[r] = (vSB[r] + xB) * 0.5f;
                const bool sA = (vSA[r] >= 0.5f), sB = (vSB[r] >= 0.5f);
                if (sA) vSA[r] = 0.f;
                if (sB) vSB[r] = 0.f;
                const size_t off = ((size_t)((b * TT + t) * LL + l)) * DD;
                S2[off + cb]      = sA ? __float2bfloat16(1.f) : __float2bfloat16(0.f);
                S2[off + cb + 32] = sB ? __float2bfloat16(1.f) : __float2bfloat16(0.f);
            }
        }
        __syncthreads();
    }
}

// ---------------------------------------------------------------------------
extern "C" void kernel_launch(void* const* d_in, const int* in_sizes, int n_in,
                              void* d_out, int out_size)
{
    const float* x   = (const float*)d_in[0];
    const float* Wq  = (const float*)d_in[1];
    const float* bq  = (const float*)d_in[2];
    const float* gq  = (const float*)d_in[3];
    const float* beq = (const float*)d_in[4];
    const float* Wk  = (const float*)d_in[5];
    const float* bk  = (const float*)d_in[6];
    const float* gk  = (const float*)d_in[7];
    const float* bek = (const float*)d_in[8];
    const float* Wv  = (const float*)d_in[9];
    const float* bv  = (const float*)d_in[10];
    const float* gv  = (const float*)d_in[11];
    const float* bev = (const float*)d_in[12];
    const float* Wl  = (const float*)d_in[13];
    const float* bl_ = (const float*)d_in[14];
    const float* gl  = (const float*)d_in[15];
    const float* bel = (const float*)d_in[16];
    float* out = (float*)d_out;

    float *Yq, *Yk, *Yv;
    __nv_bfloat16 *xs, *ws, *s2b;
    unsigned long long *qb, *kb, *vb;
    cudaGetSymbolAddress((void**)&Yq,  g_Yq);
    cudaGetSymbolAddress((void**)&Yk,  g_Yk);
    cudaGetSymbolAddress((void**)&Yv,  g_Yv);
    cudaGetSymbolAddress((void**)&xs,  g_xs);
    cudaGetSymbolAddress((void**)&ws,  g_ws);
    cudaGetSymbolAddress((void**)&s2b, g_s2b);
    cudaGetSymbolAddress((void**)&qb,  g_qb);
    cudaGetSymbolAddress((void**)&kb,  g_kb);
    cudaGetSymbolAddress((void**)&vb,  g_vb);

    const int SMEM6 = 4 * (3 * 4096 + 3 * 4096);   // 98304
    const int SMEM3 = 4 * (1 * 4096 + 3 * 4096);   // 65536
    cudaFuncSetAttribute(gemm_pre_kernel<false>,
                         cudaFuncAttributeMaxDynamicSharedMemorySize, SMEM6);
    cudaFuncSetAttribute(gemm_pre_kernel<true>,
                         cudaFuncAttributeMaxDynamicSharedMemorySize, SMEM3);

    const size_t nW = (size_t)DD * DD;

    // One launch for all splits (x + 4 weights).
    split_all_kernel<<<NXB + 4 * 256, 256>>>(x, xs, Wq, Wk, Wv, Wl, ws);

    const dim3 ggridQKV(DD / 128, ROWS / 128, 3);   // (4, 196, 3)
    const dim3 ggridL(DD / 128, ROWS / 128, 1);
    const int nLN = (BB * LL) / 8;                  // 784
    const dim3 glngrid(nLN, 3);

    gemm_pre_kernel<false><<<ggridQKV, 256, SMEM6>>>(
        xs, ws, bq, bk, bv, Yq, Yk, Yv);

    ln_lif3_kernel<<<glngrid, 256>>>(Yq, Yk, Yv, gq, gk, gv,
                                     beq, bek, bev, qb, kb, vb);

    attn_lif_kernel<<<BB * HH * 4, 256>>>(qb, kb, vb, s2b);

    gemm_pre_kernel<true><<<ggridL, 256, SMEM3>>>(
        s2b, ws + 9*nW, bl_, bl_, bl_, Yq, Yq, Yq);
    ln_lif_kernel<<<nLN, 256>>>(Yq, gl, bel, 1.0f, nullptr, out);
}

// round 16
// speedup vs baseline: 1.0255x; 1.0255x over previous
#include <cuda_runtime.h>
#include <cuda_bf16.h>
#include <cstdint>
#include <math.h>

// Shapes (fixed)
#define BB 32
#define TT 4
#define LL 196
#define DD 512
#define HH 8
#define ROWS (BB*TT*LL)          // 25088

// Scratch (device globals)
__device__ float g_Yq[(size_t)ROWS * DD];
__device__ float g_Yk[(size_t)ROWS * DD];
__device__ float g_Yv[(size_t)ROWS * DD];
__device__ __nv_bfloat16 g_xs[3 * (size_t)ROWS * DD];   // x split planes
__device__ __nv_bfloat16 g_ws[12 * (size_t)DD * DD];    // 4 weights x 3 planes
__device__ __nv_bfloat16 g_s2b[(size_t)ROWS * DD];      // attn-LIF spikes (bf16 exact)
__device__ unsigned long long g_qb[TT*BB*HH*LL];
__device__ unsigned long long g_kb[TT*BB*HH*LL];
__device__ unsigned long long g_vb[TT*BB*HH*LL];
__device__ uint32_t g_M[(size_t)TT*BB*HH * 64 * 16];    // M = K^T V, u8x4 packed

// ---------------------------------------------------------------------------
// split helpers (bf16 3-way: residual ~2^-27 — the proven-safe class)
// ---------------------------------------------------------------------------
__device__ __forceinline__ void split3(float f, float& s0, float& s1, float& s2) {
    s0 = __bfloat162float(__float2bfloat16_rn(f));
    float r1 = f - s0;
    s1 = __bfloat162float(__float2bfloat16_rn(r1));
    s2 = r1 - s1;
}

__device__ __forceinline__ void split_store(
    const float* __restrict__ X, __nv_bfloat16* __restrict__ P0,
    __nv_bfloat16* __restrict__ P1, __nv_bfloat16* __restrict__ P2, size_t idx)
{
    float4 v = *(const float4*)(X + idx);
    float a0,a1,a2,b0,b1,b2,c0,c1,c2,d0,d1,d2;
    split3(v.x, a0,a1,a2); split3(v.y, b0,b1,b2);
    split3(v.z, c0,c1,c2); split3(v.w, d0,d1,d2);
    *(__nv_bfloat162*)(P0 + idx)     = __nv_bfloat162(__float2bfloat16_rn(a0), __float2bfloat16_rn(b0));
    *(__nv_bfloat162*)(P0 + idx + 2) = __nv_bfloat162(__float2bfloat16_rn(c0), __float2bfloat16_rn(d0));
    *(__nv_bfloat162*)(P1 + idx)     = __nv_bfloat162(__float2bfloat16_rn(a1), __float2bfloat16_rn(b1));
    *(__nv_bfloat162*)(P1 + idx + 2) = __nv_bfloat162(__float2bfloat16_rn(c1), __float2bfloat16_rn(d1));
    *(__nv_bfloat162*)(P2 + idx)     = __nv_bfloat162(__float2bfloat16_rn(a2), __float2bfloat16_rn(b2));
    *(__nv_bfloat162*)(P2 + idx + 2) = __nv_bfloat162(__float2bfloat16_rn(c2), __float2bfloat16_rn(d2));
}

#define NXB ((unsigned)(((size_t)ROWS * DD) / 1024))   // 12544

__global__ void __launch_bounds__(256) split_all_kernel(
    const float* __restrict__ X, __nv_bfloat16* __restrict__ XS,
    const float* __restrict__ W0, const float* __restrict__ W1,
    const float* __restrict__ W2, const float* __restrict__ W3,
    __nv_bfloat16* __restrict__ WS)
{
    const size_t nX = (size_t)ROWS * DD;
    const size_t nW = (size_t)DD * DD;
    if (blockIdx.x < NXB) {
        const size_t idx = ((size_t)blockIdx.x * 256 + threadIdx.x) * 4;
        if (idx < nX) split_store(X, XS, XS + nX, XS + 2 * nX, idx);
    } else {
        const unsigned wb = blockIdx.x - NXB;
        const int wsel = wb >> 8;
        const float* W = (wsel == 0) ? W0 : (wsel == 1) ? W1 : (wsel == 2) ? W2 : W3;
        __nv_bfloat16* base = WS + (size_t)wsel * 3 * nW;
        const size_t idx = ((size_t)(wb & 255) * 256 + threadIdx.x) * 4;
        if (idx < nW) split_store(W, base, base + nW, base + 2 * nW, idx);
    }
}

// ---------------------------------------------------------------------------
// bf16x3 GEMM (R12 measured-best config; bit-identical results).
// ---------------------------------------------------------------------------
__device__ __forceinline__ void mma_bf16(float* c, const uint32_t* a, const uint32_t* b) {
    asm volatile(
        "mma.sync.aligned.m16n8k16.row.col.f32.bf16.bf16.f32 "
        "{%0,%1,%2,%3}, {%4,%5,%6,%7}, {%8,%9}, {%0,%1,%2,%3};\n"
        : "+f"(c[0]), "+f"(c[1]), "+f"(c[2]), "+f"(c[3])
        : "r"(a[0]), "r"(a[1]), "r"(a[2]), "r"(a[3]), "r"(b[0]), "r"(b[1]));
}

__device__ __forceinline__ void ldsm_x4(uint32_t& d0, uint32_t& d1, uint32_t& d2,
                                        uint32_t& d3, uint32_t addr) {
    asm volatile("ldmatrix.sync.aligned.m8n8.x4.shared.b16 {%0,%1,%2,%3}, [%4];"
                 : "=r"(d0), "=r"(d1), "=r"(d2), "=r"(d3) : "r"(addr));
}

template <bool EXACT_A>
__global__ void __launch_bounds__(256, 2) gemm_pre_kernel(
    const __nv_bfloat16* __restrict__ Ap,
    const __nv_bfloat16* __restrict__ BpBase,
    const float* __restrict__ bias0, const float* __restrict__ bias1,
    const float* __restrict__ bias2,
    float* __restrict__ C0, float* __restrict__ C1, float* __restrict__ C2)
{
    constexpr int APL = EXACT_A ? 1 : 3;
    constexpr int ASZ = APL * 4096;
    constexpr int BSZ = 3 * 4096;
    constexpr int STG = ASZ + BSZ;

    extern __shared__ char smem[];
    const uint32_t sbase = (uint32_t)__cvta_generic_to_shared(smem);

    const int z = blockIdx.z;
    const __nv_bfloat16* Bp = BpBase + (size_t)z * 3 * ((size_t)DD * DD);
    const float* bias = (z == 0) ? bias0 : (z == 1) ? bias1 : bias2;
    float* C = (z == 0) ? C0 : (z == 1) ? C1 : C2;

    const int tid = threadIdx.x;
    const int bn = blockIdx.x * 128, bm = blockIdx.y * 128;
    const int w = tid >> 5, lane = tid & 31;
    const int wm = (w & 1) * 64, wn = (w >> 1) * 32;
    const int g = lane >> 2, tg = lane & 3;

    const int lrow = tid >> 1;
    const int kh = tid & 1;
    const int dstoff = (kh * 512 + lrow * 4) * 4;

    const int rowW = lane & 7;
    const int plus8 = (lane >> 3) & 1;
    const int halfsel = (lane >> 4) & 1;
    const int aLane = halfsel * 2048 + (wm + plus8 * 8 + rowW) * 16;
    const int bLane = (wn + (lane >> 3) * 8 + rowW) * 16;

    float acc[4][4][4];
#pragma unroll
    for (int mi = 0; mi < 4; mi++)
#pragma unroll
        for (int ni = 0; ni < 4; ni++)
#pragma unroll
            for (int r = 0; r < 4; r++) acc[mi][ni][r] = 0.f;

    auto stage_load = [&](int buf, int k0) {
        const uint32_t aBase = sbase + buf * STG + dstoff;
        const uint32_t bBase = sbase + buf * STG + ASZ + dstoff;
#pragma unroll
        for (int p = 0; p < APL; p++) {
            const __nv_bfloat16* src = Ap + (size_t)p * ((size_t)ROWS * DD)
                                          + (size_t)(bm + lrow) * DD + k0 + kh * 8;
            asm volatile("cp.async.cg.shared.global [%0], [%1], 16;\n"
                         :: "r"(aBase + p * 4096), "l"(src));
        }
#pragma unroll
        for (int p = 0; p < 3; p++) {
            const __nv_bfloat16* src = Bp + (size_t)p * ((size_t)DD * DD)
                                          + (size_t)(bn + lrow) * DD + k0 + kh * 8;
            asm volatile("cp.async.cg.shared.global [%0], [%1], 16;\n"
                         :: "r"(bBase + p * 4096), "l"(src));
        }
        asm volatile("cp.async.commit_group;\n");
    };

    stage_load(0, 0);
    stage_load(1, 16);
    stage_load(2, 32);

    for (int s = 0; s < 32; s++) {
        const int buf = s & 3;
        if (s < 30) { asm volatile("cp.async.wait_group 2;\n"); }
        else        { asm volatile("cp.async.wait_group 0;\n"); }
        __syncthreads();

        const uint32_t stA = sbase + buf * STG;
        const uint32_t stB = stA + ASZ;

        uint32_t bf[3][4][2];
#pragma unroll
        for (int p = 0; p < 3; p++) {
            ldsm_x4(bf[p][0][0], bf[p][1][0], bf[p][2][0], bf[p][3][0],
                    stB + p * 4096 + bLane);
            ldsm_x4(bf[p][0][1], bf[p][1][1], bf[p][2][1], bf[p][3][1],
                    stB + p * 4096 + 2048 + bLane);
        }

        constexpr int NT = EXACT_A ? 3 : 6;
        const int ta[6] = {0, 0, 0, 1, 1, 2};
        const int tb[6] = {0, 1, 2, 0, 1, 0};

#pragma unroll
        for (int mi = 0; mi < 4; mi++) {
            uint32_t af[APL][4];
#pragma unroll
            for (int p = 0; p < APL; p++)
                ldsm_x4(af[p][0], af[p][1], af[p][2], af[p][3],
                        stA + p * 4096 + aLane + mi * 256);
#pragma unroll
            for (int t = 0; t < NT; t++) {
                const uint32_t* aF = af[EXACT_A ? 0 : ta[t]];
#pragma unroll
                for (int ni = 0; ni < 4; ni++) {
                    uint32_t bb[2] = { bf[tb[t]][ni][0], bf[tb[t]][ni][1] };
                    mma_bf16(acc[mi][ni], aF, bb);
                }
            }
        }

        if (s + 3 < 32) stage_load((s + 3) & 3, (s + 3) * 16);
    }

#pragma unroll
    for (int mi = 0; mi < 4; mi++) {
        const int row = bm + wm + mi * 16 + g;
#pragma unroll
        for (int ni = 0; ni < 4; ni++) {
            const int col = bn + wn + ni * 8 + tg * 2;
            const float b0 = bias[col], b1 = bias[col + 1];
            *(float2*)(C + (size_t)row * DD + col) =
                make_float2(acc[mi][ni][0] + b0, acc[mi][ni][1] + b1);
            *(float2*)(C + (size_t)(row + 8) * DD + col) =
                make_float2(acc[mi][ni][2] + b0, acc[mi][ni][3] + b1);
        }
    }
}

// ---------------------------------------------------------------------------
// Barrier-free LayerNorm + LIF core (bit-identical sums).
// ---------------------------------------------------------------------------
__device__ __forceinline__ void ln_lif_body(
    const float* __restrict__ Y, const float* __restrict__ g,
    const float* __restrict__ be, float thr,
    unsigned long long* __restrict__ bits, float* __restrict__ outf,
    int wg)
{
    const int b = wg / LL, l = wg % LL;
    const int lane = threadIdx.x & 31;

    float vA[8], vB[8];
#pragma unroll
    for (int i = 0; i < 8; i++) { vA[i] = 0.f; vB[i] = 0.f; }

    for (int t = 0; t < TT; t++) {
        const size_t roff = ((size_t)((b * TT + t) * LL + l)) * DD;
        float yA[8], yB[8], s[8];
#pragma unroll
        for (int i = 0; i < 8; i++) {
            yA[i] = Y[roff + i * 64 + lane];
            yB[i] = Y[roff + i * 64 + 32 + lane];
            s[i] = yA[i] + yB[i];
        }
#pragma unroll
        for (int o = 16; o; o >>= 1)
#pragma unroll
            for (int i = 0; i < 8; i++) s[i] += __shfl_xor_sync(0xffffffffu, s[i], o);
        float S = 0.f;
#pragma unroll
        for (int i = 0; i < 8; i++) S += s[i];
        const float mean = S * (1.f / 512.f);

        float q[8];
#pragma unroll
        for (int i = 0; i < 8; i++) {
            const float dA = yA[i] - mean, dB = yB[i] - mean;
            q[i] = dA * dA + dB * dB;
        }
#pragma unroll
        for (int o = 16; o; o >>= 1)
#pragma unroll
            for (int i = 0; i < 8; i++) q[i] += __shfl_xor_sync(0xffffffffu, q[i], o);
        float Q = 0.f;
#pragma unroll
        for (int i = 0; i < 8; i++) Q += q[i];
        const float var = Q * (1.f / 512.f);
        const float rstd = (float)(1.0 / sqrt((double)var + 1e-5));

        unsigned long long rowbits[8];
#pragma unroll
        for (int i = 0; i < 8; i++) {
            const float dA = yA[i] - mean, dB = yB[i] - mean;
            const float nA = dA * rstd * g[i * 64 + lane] + be[i * 64 + lane];
            const float nB = dB * rstd * g[i * 64 + 32 + lane] + be[i * 64 + 32 + lane];
            vA[i] = (vA[i] + nA) * 0.5f;
            vB[i] = (vB[i] + nB) * 0.5f;
            const bool sA = (vA[i] >= thr), sB = (vB[i] >= thr);
            if (sA) vA[i] = 0.f;
            if (sB) vB[i] = 0.f;
            if (bits) {
                unsigned mA = __ballot_sync(0xffffffffu, sA);
                unsigned mB = __ballot_sync(0xffffffffu, sB);
                rowbits[i] = (unsigned long long)mA | ((unsigned long long)mB << 32);
            } else {
                outf[roff + i * 64 + lane]      = sA ? 1.f : 0.f;
                outf[roff + i * 64 + 32 + lane] = sB ? 1.f : 0.f;
            }
        }
        if (bits && lane == 0) {
#pragma unroll
            for (int i = 0; i < 8; i++)
                bits[((size_t)(t * BB + b) * HH + i) * LL + l] = rowbits[i];
        }
    }
}

__global__ void __launch_bounds__(256, 3) ln_lif3_kernel(
    const float* __restrict__ Y0, const float* __restrict__ Y1,
    const float* __restrict__ Y2,
    const float* __restrict__ g0, const float* __restrict__ g1,
    const float* __restrict__ g2,
    const float* __restrict__ be0, const float* __restrict__ be1,
    const float* __restrict__ be2,
    unsigned long long* __restrict__ b0, unsigned long long* __restrict__ b1,
    unsigned long long* __restrict__ b2)
{
    const int wg = blockIdx.x * 8 + (threadIdx.x >> 5);
    if (wg >= BB * LL) return;
    const int sel = blockIdx.y;
    const float* Y  = (sel == 0) ? Y0 : (sel == 1) ? Y1 : Y2;
    const float* g  = (sel == 0) ? g0 : (sel == 1) ? g1 : g2;
    const float* be = (sel == 0) ? be0 : (sel == 1) ? be1 : be2;
    unsigned long long* bits = (sel == 0) ? b0 : (sel == 1) ? b1 : b2;
    ln_lif_body(Y, g, be, 1.0f, bits, nullptr, wg);
}

__global__ void __launch_bounds__(256, 3) ln_lif_kernel(
    const float* __restrict__ Y, const float* __restrict__ g,
    const float* __restrict__ be, float thr,
    unsigned long long* __restrict__ bits, float* __restrict__ outf)
{
    const int wg = blockIdx.x * 8 + (threadIdx.x >> 5);
    if (wg >= BB * LL) return;
    ln_lif_body(Y, g, be, thr, bits, outf, wg);
}

// ---------------------------------------------------------------------------
// Kernel A: build M = K^T V once per (t,b,h); write u8x4-packed to gmem.
// grid = TT*BB*HH = 1024 blocks. Exact integer math.
// ---------------------------------------------------------------------------
__global__ void __launch_bounds__(256) build_m_kernel(
    const unsigned long long* __restrict__ kb,
    const unsigned long long* __restrict__ vb,
    uint32_t* __restrict__ Mout)
{
    __shared__ unsigned long long ks[LL], vs[LL];
    __shared__ uint32_t sKc[64 * 9], sVc[64 * 9];

    const int blk = blockIdx.x;                  // (t*BB + b)*HH + h
    const size_t base = (size_t)blk * LL;
    const int tid = threadIdx.x, w = tid >> 5, lane = tid & 31;

    if (tid < LL) { ks[tid] = kb[base + tid]; vs[tid] = vb[base + tid]; }
    __syncthreads();

    // bitset transpose via ballot: warp w -> j-chunk w (0..6)
    if (w < 7) {
        const int j = w * 32 + lane;
        const unsigned long long kv = (j < LL) ? ks[j] : 0ull;
        const unsigned long long vv = (j < LL) ? vs[j] : 0ull;
#pragma unroll
        for (int c = 0; c < 64; c++) {
            unsigned mk = __ballot_sync(0xffffffffu, (unsigned)((kv >> c) & 1ull));
            unsigned mv = __ballot_sync(0xffffffffu, (unsigned)((vv >> c) & 1ull));
            if (lane == 0) { sKc[c * 9 + w] = mk; sVc[c * 9 + w] = mv; }
        }
    }
    __syncthreads();

    // M build: thread -> c' = tid&63, words i = (tid>>6)*4 .. +3; write gmem.
    const int cq = tid & 63;
    const int ib = (tid >> 6) * 4;
    uint32_t vc[7];
#pragma unroll
    for (int u = 0; u < 7; u++) vc[u] = sVc[cq * 9 + u];
    uint32_t* mg = Mout + (size_t)blk * 1024 + cq * 16;
#pragma unroll
    for (int wd = 0; wd < 4; wd++) {
        const int i = ib + wd;
        uint32_t word = 0;
#pragma unroll
        for (int r = 0; r < 4; r++) {
            const int c = 4 * i + r;
            int s = 0;
#pragma unroll
            for (int u = 0; u < 7; u++) s += __popc(sKc[c * 9 + u] & vc[u]);
            word |= (uint32_t)s << (8 * r);
        }
        mg[i] = word;
    }
}

// ---------------------------------------------------------------------------
// Kernel B: O = Q @ M * 0.25 + LIF over t, emit bf16 spikes.
// grid = (b,h,quarter); M loaded from gmem (L2-resident). Exact.
// Qw is 16B-aligned (uint4 row reads).
// ---------------------------------------------------------------------------
#define QROWS 49

__global__ void __launch_bounds__(256) attn_lif_kernel(
    const unsigned long long* __restrict__ qb,
    const uint32_t* __restrict__ Min,
    __nv_bfloat16* __restrict__ S2)
{
    __shared__ __align__(16) uint32_t Qw[QROWS * 16];
    __shared__ __align__(16) unsigned long long qs[QROWS + 1];

    const int blk = blockIdx.x;              // b*32 + h*4 + qr
    const int qr = blk & 3;
    const int h = (blk >> 2) & 7;
    const int b = blk >> 5;
    const int l0 = qr * QROWS;
    const int tid = threadIdx.x, w = tid >> 5, lane = tid & 31;
    const int cb = h * 64 + lane;

    float vSA[7], vSB[7];
#pragma unroll
    for (int r = 0; r < 7; r++) { vSA[r] = 0.f; vSB[r] = 0.f; }

    for (int t = 0; t < TT; t++) {
        const int mblk = (t * BB + b) * HH + h;
        const size_t qbase = (size_t)mblk * LL + l0;

        // Load M columns for this warp's c' lanes (coalesced 64B/lane chunks).
        const uint32_t* mg = Min + (size_t)mblk * 1024;
        uint32_t MA[16], MB[16];
#pragma unroll
        for (int i4 = 0; i4 < 16; i4 += 4) {
            *(uint4*)&MA[i4] = *(const uint4*)(mg + lane * 16 + i4);
            *(uint4*)&MB[i4] = *(const uint4*)(mg + (lane + 32) * 16 + i4);
        }

        if (tid < QROWS) qs[tid] = qb[qbase + tid];
        __syncthreads();

        for (int idx = tid; idx < QROWS * 16; idx += 256) {
            const int lr = idx >> 4, i = idx & 15;
            const uint32_t nib = (uint32_t)(qs[lr] >> (4 * i)) & 0xFu;
            Qw[idx] = (nib * 0x00204081u) & 0x01010101u;
        }
        __syncthreads();

#pragma unroll
        for (int r = 0; r < 7; r++) {
            const int lr = w + 8 * r;
            if (lr < QROWS) {
                const int l = l0 + lr;
                uint32_t acc0 = 0, acc1 = 0;
                const uint32_t* qrow = &Qw[lr * 16];
#pragma unroll
                for (int i4 = 0; i4 < 16; i4 += 4) {
                    uint4 qv = *(const uint4*)(qrow + i4);
                    acc0 = __dp4a(qv.x, MA[i4 + 0], acc0);
                    acc1 = __dp4a(qv.x, MB[i4 + 0], acc1);
                    acc0 = __dp4a(qv.y, MA[i4 + 1], acc0);
                    acc1 = __dp4a(qv.y, MB[i4 + 1], acc1);
                    acc0 = __dp4a(qv.z, MA[i4 + 2], acc0);
                    acc1 = __dp4a(qv.z, MB[i4 + 2], acc1);
                    acc0 = __dp4a(qv.w, MA[i4 + 3], acc0);
                    acc1 = __dp4a(qv.w, MB[i4 + 3], acc1);
                }
                const float xA = (float)(int)acc0 * 0.25f;
                const float xB = (float)(int)acc1 * 0.25f;
                vSA[r] = (vSA[r] + xA) * 0.5f;
                vSB[r] = (vSB[r] + xB) * 0.5f;
                const bool sA = (vSA[r] >= 0.5f), sB = (vSB[r] >= 0.5f);
                if (sA) vSA[r] = 0.f;
                if (sB) vSB[r] = 0.f;
                const size_t off = ((size_t)((b * TT + t) * LL + l)) * DD;
                S2[off + cb]      = sA ? __float2bfloat16(1.f) : __float2bfloat16(0.f);
                S2[off + cb + 32] = sB ? __float2bfloat16(1.f) : __float2bfloat16(0.f);
            }
        }
        __syncthreads();
    }
}

// ---------------------------------------------------------------------------
extern "C" void kernel_launch(void* const* d_in, const int* in_sizes, int n_in,
                              void* d_out, int out_size)
{
    const float* x   = (const float*)d_in[0];
    const float* Wq  = (const float*)d_in[1];
    const float* bq  = (const float*)d_in[2];
    const float* gq  = (const float*)d_in[3];
    const float* beq = (const float*)d_in[4];
    const float* Wk  = (const float*)d_in[5];
    const float* bk  = (const float*)d_in[6];
    const float* gk  = (const float*)d_in[7];
    const float* bek = (const float*)d_in[8];
    const float* Wv  = (const float*)d_in[9];
    const float* bv  = (const float*)d_in[10];
    const float* gv  = (const float*)d_in[11];
    const float* bev = (const float*)d_in[12];
    const float* Wl  = (const float*)d_in[13];
    const float* bl_ = (const float*)d_in[14];
    const float* gl  = (const float*)d_in[15];
    const float* bel = (const float*)d_in[16];
    float* out = (float*)d_out;

    float *Yq, *Yk, *Yv;
    __nv_bfloat16 *xs, *ws, *s2b;
    unsigned long long *qb, *kb, *vb;
    uint32_t* Mg;
    cudaGetSymbolAddress((void**)&Yq,  g_Yq);
    cudaGetSymbolAddress((void**)&Yk,  g_Yk);
    cudaGetSymbolAddress((void**)&Yv,  g_Yv);
    cudaGetSymbolAddress((void**)&xs,  g_xs);
    cudaGetSymbolAddress((void**)&ws,  g_ws);
    cudaGetSymbolAddress((void**)&s2b, g_s2b);
    cudaGetSymbolAddress((void**)&qb,  g_qb);
    cudaGetSymbolAddress((void**)&kb,  g_kb);
    cudaGetSymbolAddress((void**)&vb,  g_vb);
    cudaGetSymbolAddress((void**)&Mg,  g_M);

    const int SMEM6 = 4 * (3 * 4096 + 3 * 4096);   // 98304
    const int SMEM3 = 4 * (1 * 4096 + 3 * 4096);   // 65536
    cudaFuncSetAttribute(gemm_pre_kernel<false>,
                         cudaFuncAttributeMaxDynamicSharedMemorySize, SMEM6);
    cudaFuncSetAttribute(gemm_pre_kernel<true>,
                         cudaFuncAttributeMaxDynamicSharedMemorySize, SMEM3);

    const size_t nW = (size_t)DD * DD;

    split_all_kernel<<<NXB + 4 * 256, 256>>>(x, xs, Wq, Wk, Wv, Wl, ws);

    const dim3 ggridQKV(DD / 128, ROWS / 128, 3);   // (4, 196, 3)
    const dim3 ggridL(DD / 128, ROWS / 128, 1);
    const int nLN = (BB * LL) / 8;                  // 784
    const dim3 glngrid(nLN, 3);

    gemm_pre_kernel<false><<<ggridQKV, 256, SMEM6>>>(
        xs, ws, bq, bk, bv, Yq, Yk, Yv);

    ln_lif3_kernel<<<glngrid, 256>>>(Yq, Yk, Yv, gq, gk, gv,
                                     beq, bek, bev, qb, kb, vb);

    build_m_kernel<<<TT * BB * HH, 256>>>(kb, vb, Mg);
    attn_lif_kernel<<<BB * HH * 4, 256>>>(qb, Mg, s2b);

    gemm_pre_kernel<true><<<ggridL, 256, SMEM3>>>(
        s2b, ws + 9*nW, bl_, bl_, bl_, Yq, Yq, Yq);
    ln_lif_kernel<<<nLN, 256>>>(Yq, gl, bel, 1.0f, nullptr, out);
}